// round 7
// baseline (speedup 1.0000x reference)
#include <cuda_runtime.h>
#include <cstdint>

// Z gate (DIM=2, S=1) on wires {0,5,11} of a 24-qubit register.
//   out[n] = (-1)^popc(n & SIGN_MASK) * x_real[n]   (N float32)
// SIGN_MASK bits 23,18,12 -> sign constant over each 4096-element aligned block.
//
// CTA = 1024 consecutive float4s (4096 elems): one uniform sign per CTA.
// Warp-strided accesses -> every LDG/STG.128 is a contiguous 4KB warp access.
// Default cache policy: input+output (~128MB) nearly fit the 126MB L2, so
// keeping both resident lets replays hit L2 and elide DRAM writebacks
// (evict-first .cs hints measurably hurt here: DRAM pinned at 58%).

#define SIGN_MASK ((1u << 23) | (1u << 18) | (1u << 12))
#define V4_PER_BLOCK 1024u
#define THREADS 256u

__global__ void __launch_bounds__(256) z_phase_kernel(
    const float4* __restrict__ xr,
    float4* __restrict__ out)
{
    unsigned base = blockIdx.x * V4_PER_BLOCK;
    float s = (__popc((base << 2) & SIGN_MASK) & 1) ? -1.0f : 1.0f;

    unsigned i0 = base + threadIdx.x;

    float4 a = __ldg(&xr[i0 + 0u * THREADS]);
    float4 b = __ldg(&xr[i0 + 1u * THREADS]);
    float4 c = __ldg(&xr[i0 + 2u * THREADS]);
    float4 d = __ldg(&xr[i0 + 3u * THREADS]);

    a.x *= s; a.y *= s; a.z *= s; a.w *= s;
    b.x *= s; b.y *= s; b.z *= s; b.w *= s;
    c.x *= s; c.y *= s; c.z *= s; c.w *= s;
    d.x *= s; d.y *= s; d.z *= s; d.w *= s;

    out[i0 + 0u * THREADS] = a;
    out[i0 + 1u * THREADS] = b;
    out[i0 + 2u * THREADS] = c;
    out[i0 + 3u * THREADS] = d;
}

extern "C" void kernel_launch(void* const* d_in, const int* in_sizes, int n_in,
                              void* d_out, int out_size)
{
    const float4* xr = (const float4*)d_in[0];
    float4* out = (float4*)d_out;

    const unsigned n_vec4 = (1u << 24) / 4u;           // 4,194,304 float4s
    const unsigned blocks = n_vec4 / V4_PER_BLOCK;     // 4096

    z_phase_kernel<<<blocks, THREADS>>>(xr, out);
}

// round 8
// speedup vs baseline: 1.0977x; 1.0977x over previous
#include <cuda_runtime.h>
#include <cstdint>

// Z gate (DIM=2, S=1) on wires {0,5,11} of a 24-qubit register.
//   out[n] = (-1)^popc(n & SIGN_MASK) * x_real[n]   (N float32)
// SIGN_MASK bits 23,18,12 -> sign constant over each 4096-element aligned block.
//
// CTA = 1024 consecutive float4s: one uniform sign per CTA; warp-strided
// accesses -> every LDG/STG.128 is a contiguous 4KB warp access, MLP=4.
//
// Mixed cache policy (the key change): loads DEFAULT so the 64MB input stays
// resident in the 126MB L2 across graph replays; stores EVICT-FIRST (.cs) so
// the write-only output doesn't evict the input. Prior rounds measured:
// matched .cs/.cs and default/default both leave DRAM carrying writes + ~21MB
// of read misses (85MB); this should cut DRAM to ~write-only.

#define SIGN_MASK ((1u << 23) | (1u << 18) | (1u << 12))
#define V4_PER_BLOCK 1024u
#define THREADS 256u

__global__ void __launch_bounds__(256) z_phase_kernel(
    const float4* __restrict__ xr,
    float4* __restrict__ out)
{
    unsigned base = blockIdx.x * V4_PER_BLOCK;
    float s = (__popc((base << 2) & SIGN_MASK) & 1) ? -1.0f : 1.0f;

    unsigned i0 = base + threadIdx.x;

    float4 a = __ldg(&xr[i0 + 0u * THREADS]);
    float4 b = __ldg(&xr[i0 + 1u * THREADS]);
    float4 c = __ldg(&xr[i0 + 2u * THREADS]);
    float4 d = __ldg(&xr[i0 + 3u * THREADS]);

    a.x *= s; a.y *= s; a.z *= s; a.w *= s;
    b.x *= s; b.y *= s; b.z *= s; b.w *= s;
    c.x *= s; c.y *= s; c.z *= s; c.w *= s;
    d.x *= s; d.y *= s; d.z *= s; d.w *= s;

    __stcs(&out[i0 + 0u * THREADS], a);
    __stcs(&out[i0 + 1u * THREADS], b);
    __stcs(&out[i0 + 2u * THREADS], c);
    __stcs(&out[i0 + 3u * THREADS], d);
}

extern "C" void kernel_launch(void* const* d_in, const int* in_sizes, int n_in,
                              void* d_out, int out_size)
{
    const float4* xr = (const float4*)d_in[0];
    float4* out = (float4*)d_out;

    const unsigned n_vec4 = (1u << 24) / 4u;           // 4,194,304 float4s
    const unsigned blocks = n_vec4 / V4_PER_BLOCK;     // 4096

    z_phase_kernel<<<blocks, THREADS>>>(xr, out);
}

// round 9
// speedup vs baseline: 1.1884x; 1.0826x over previous
#include <cuda_runtime.h>
#include <cstdint>

// Z gate (DIM=2, S=1) on wires {0,5,11} of a 24-qubit register.
//   out[n] = (-1)^popc(n & SIGN_MASK) * x_real[n]   (N float32)
// SIGN_MASK bits 23,18,12 -> sign constant over each 4096-element block,
// and flips exactly at the midpoint of an 8192-element block (bit 12 toggles).
//
// CTA = 2048 consecutive float4s (8192 elems). Warp-strided accesses: thread
// handles base + k*256 + tid, k=0..7 -> every LDG/STG.128 is a contiguous,
// fully-coalesced 4KB warp access; 8 independent loads in flight per thread.
// First 4 chunks use sign s, last 4 use -s (bit-12 flip).
// Cache policy proved irrelevant over R5-R8 (DRAM pinned ~55-60% for all
// combinations); using default loads + streaming stores.

#define SIGN_MASK ((1u << 23) | (1u << 18) | (1u << 12))
#define V4_PER_BLOCK 2048u
#define THREADS 256u

__global__ void __launch_bounds__(256) z_phase_kernel(
    const float4* __restrict__ xr,
    float4* __restrict__ out)
{
    unsigned base = blockIdx.x * V4_PER_BLOCK;
    float s = (__popc((base << 2) & SIGN_MASK) & 1) ? -1.0f : 1.0f;

    unsigned i0 = base + threadIdx.x;

    float4 v0 = __ldg(&xr[i0 + 0u * THREADS]);
    float4 v1 = __ldg(&xr[i0 + 1u * THREADS]);
    float4 v2 = __ldg(&xr[i0 + 2u * THREADS]);
    float4 v3 = __ldg(&xr[i0 + 3u * THREADS]);
    float4 v4 = __ldg(&xr[i0 + 4u * THREADS]);
    float4 v5 = __ldg(&xr[i0 + 5u * THREADS]);
    float4 v6 = __ldg(&xr[i0 + 6u * THREADS]);
    float4 v7 = __ldg(&xr[i0 + 7u * THREADS]);

    float t = -s;  // second 4096-element half: bit 12 set -> sign flipped

    v0.x *= s; v0.y *= s; v0.z *= s; v0.w *= s;
    v1.x *= s; v1.y *= s; v1.z *= s; v1.w *= s;
    v2.x *= s; v2.y *= s; v2.z *= s; v2.w *= s;
    v3.x *= s; v3.y *= s; v3.z *= s; v3.w *= s;
    v4.x *= t; v4.y *= t; v4.z *= t; v4.w *= t;
    v5.x *= t; v5.y *= t; v5.z *= t; v5.w *= t;
    v6.x *= t; v6.y *= t; v6.z *= t; v6.w *= t;
    v7.x *= t; v7.y *= t; v7.z *= t; v7.w *= t;

    __stcs(&out[i0 + 0u * THREADS], v0);
    __stcs(&out[i0 + 1u * THREADS], v1);
    __stcs(&out[i0 + 2u * THREADS], v2);
    __stcs(&out[i0 + 3u * THREADS], v3);
    __stcs(&out[i0 + 4u * THREADS], v4);
    __stcs(&out[i0 + 5u * THREADS], v5);
    __stcs(&out[i0 + 6u * THREADS], v6);
    __stcs(&out[i0 + 7u * THREADS], v7);
}

extern "C" void kernel_launch(void* const* d_in, const int* in_sizes, int n_in,
                              void* d_out, int out_size)
{
    const float4* xr = (const float4*)d_in[0];
    float4* out = (float4*)d_out;

    const unsigned n_vec4 = (1u << 24) / 4u;           // 4,194,304 float4s
    const unsigned blocks = n_vec4 / V4_PER_BLOCK;     // 2048

    z_phase_kernel<<<blocks, THREADS>>>(xr, out);
}